// round 15
// baseline (speedup 1.0000x reference)
#include <cuda_runtime.h>
#include <cuda_fp16.h>
#include <stdint.h>

#define B 2
#define L 2048
#define C 1024
#define H 16
#define D 64
#define L2 512
#define TD 768
#define FF 4096
#define EPS 1e-6f
#define BL 4096
#define BL2 1024
#define ZB 32
#define SCL 0.180336880f   // 0.125 * log2(e)

// ---- scratch ----
__device__ float g_mods[128 * 6 * C];
__device__ float g_x[BL * C];
__device__ half g_h[(size_t)BL * FF];
__device__ half g_act[(size_t)BL * C];
__device__ half g_ctx[BL2 * TD];
__device__ half g_sm[128 * C];
__device__ half g_qh[(size_t)ZB * L * D];
__device__ half g_kh[(size_t)ZB * L * D];
__device__ half g_v[(size_t)ZB * L * D];
// weights fp16, transposed [N][K]
__device__ half w_qkv[3*C*C];
__device__ half w_sa[C*C];
__device__ half w_q[C*C];
__device__ half w_kv[2*C*TD];
__device__ half w_ca[C*C];
__device__ half w_gu[(size_t)2*FF*C];
__device__ half w_d[(size_t)FF*C];
__device__ half w_ada[6*C*C];

// ---- helpers ----
__device__ __forceinline__ uint32_t smem_u32(const void* p) {
    uint32_t a;
    asm("{ .reg .u64 t; cvta.to.shared.u64 t, %1; cvt.u32.u64 %0, t; }" : "=r"(a) : "l"(p));
    return a;
}
__device__ __forceinline__ void cp16(uint32_t s, const void* g) {
    asm volatile("cp.async.cg.shared.global [%0], [%1], 16;" :: "r"(s), "l"(g));
}
__device__ __forceinline__ void ldsm4(uint32_t* r, uint32_t a) {
    asm volatile("ldmatrix.sync.aligned.m8n8.x4.shared.b16 {%0,%1,%2,%3}, [%4];"
        : "=r"(r[0]), "=r"(r[1]), "=r"(r[2]), "=r"(r[3]) : "r"(a));
}
__device__ __forceinline__ void ldsm4t(uint32_t* r, uint32_t a) {
    asm volatile("ldmatrix.sync.aligned.m8n8.x4.trans.shared.b16 {%0,%1,%2,%3}, [%4];"
        : "=r"(r[0]), "=r"(r[1]), "=r"(r[2]), "=r"(r[3]) : "r"(a));
}
__device__ __forceinline__ void mma16816(float* d, const uint32_t* a, uint32_t b0, uint32_t b1) {
    asm volatile("mma.sync.aligned.m16n8k16.row.col.f32.f16.f16.f32 "
        "{%0,%1,%2,%3}, {%4,%5,%6,%7}, {%8,%9}, {%0,%1,%2,%3};"
        : "+f"(d[0]), "+f"(d[1]), "+f"(d[2]), "+f"(d[3])
        : "r"(a[0]), "r"(a[1]), "r"(a[2]), "r"(a[3]), "r"(b0), "r"(b1));
}
__device__ __forceinline__ uint32_t ex2h2(float a, float b) {
    uint32_t h;
    asm("{ .reg .b32 t;\n\t"
        "cvt.rn.f16x2.f32 t, %2, %1;\n\t"
        "ex2.approx.f16x2 %0, t; }"
        : "=r"(h) : "f"(a), "f"(b));
    return h;
}
__device__ __forceinline__ float siluf(float v) { return v / (1.f + __expf(-v)); }

// ---- pipelined fp16 mma GEMM, K-chunk 128, double-buffered, fused epilogues ----
// EPI: 0 = float out (+ optional residual x + gate*acc)
//      2 = swiglu (interleaved gate/up) -> half [M][FF]
//      3 = SA qkv: rope q,k -> qh,kh; v row-major
//      4 = CA q   5 = CA kv
#define STG 98304u     // A 32KB | B 64KB

template<int EPI>
__global__ void __launch_bounds__(256) gmma(
    const half* __restrict__ Ax, const half* __restrict__ B0,
    void* __restrict__ Cout, int M, int N, int K,
    const float* __restrict__ resx, const float* __restrict__ mods,
    const float* __restrict__ bias, int goff,
    const float* __restrict__ fc, const float* __restrict__ fs,
    half* __restrict__ khp, half* __restrict__ vtp, int Lk)
{
    extern __shared__ char smem[];
    uint32_t sb = smem_u32(smem);
    const int tid = threadIdx.x, lane = tid & 31, wid = tid >> 5;
    const int wm = (wid & 1) << 6;
    const int wn = (wid >> 1) << 6;
    const int tM = blockIdx.y << 7, tN = blockIdx.x << 8;

    float acc[4][8][4];
#pragma unroll
    for (int f = 0; f < 4; f++)
#pragma unroll
        for (int n = 0; n < 8; n++)
#pragma unroll
            for (int v = 0; v < 4; v++) acc[f][n][v] = 0.f;

    const int kIters = K >> 7;

    auto load_stage = [&](int s, int k0) {
#pragma unroll
        for (int i = 0; i < 24; i++) {
            int id = tid + (i << 8);
            const half* g; uint32_t dst;
            if (id < 2048) {
                int row = id >> 4, c = id & 15;
                g = Ax + (size_t)(tM + row) * K + k0 + (c << 3);
                dst = sb + (uint32_t)s * STG + row * 256 + ((c ^ (row & 7)) << 4);
            } else {
                int a = id - 2048;
                int row = a >> 4, c = a & 15;
                g = B0 + (size_t)(tN + row) * K + k0 + (c << 3);
                dst = sb + (uint32_t)s * STG + 32768u + row * 256 + ((c ^ (row & 7)) << 4);
            }
            cp16(dst, g);
        }
    };

    load_stage(0, 0);
    asm volatile("cp.async.commit_group;");

    const int lrow = lane & 15, lch = lane >> 4;

    for (int it = 0; it < kIters; it++) {
        asm volatile("cp.async.wait_group 0;");
        __syncthreads();
        if (it + 1 < kIters) load_stage((it + 1) & 1, (it + 1) << 7);
        asm volatile("cp.async.commit_group;");

        uint32_t stg = sb + (uint32_t)(it & 1) * STG;
#pragma unroll
        for (int ks = 0; ks < 8; ks++) {
            int ch = (ks << 1) + lch;
            uint32_t a[4][4], b[4][4];
#pragma unroll
            for (int f = 0; f < 4; f++) {
                int row = wm + (f << 4) + lrow;
                ldsm4(a[f], stg + row * 256 + ((ch ^ (row & 7)) << 4));
            }
#pragma unroll
            for (int p = 0; p < 4; p++) {
                int row = wn + (p << 4) + lrow;
                ldsm4(b[p], stg + 32768u + row * 256 + ((ch ^ (row & 7)) << 4));
            }
#pragma unroll
            for (int f = 0; f < 4; f++)
#pragma unroll
                for (int n = 0; n < 8; n++)
                    mma16816(acc[f][n], a[f], b[n >> 1][n & 1], b[n >> 1][2 + (n & 1)]);
        }
    }

    const int bb = (EPI == 5) ? 0 : (tM >> 11);
#pragma unroll
    for (int f = 0; f < 4; f++) {
        int r0 = tM + wm + (f << 4) + (lane >> 2);
#pragma unroll
        for (int n = 0; n < 8; n++) {
            int col = tN + wn + (n << 3) + ((lane & 3) << 1);
            float v0 = acc[f][n][0], v1 = acc[f][n][1];
            float v2 = acc[f][n][2], v3 = acc[f][n][3];
            if (EPI == 0) {
                float* Cf = (float*)Cout;
                if (resx) {
                    float g0 = 1.f, g1 = 1.f;
                    if (mods) {
                        g0 = mods[(size_t)bb * 6 * C + goff + col]     + bias[goff + col];
                        g1 = mods[(size_t)bb * 6 * C + goff + col + 1] + bias[goff + col + 1];
                    }
                    v0 = resx[(size_t)r0 * N + col]         + g0 * v0;
                    v1 = resx[(size_t)r0 * N + col + 1]     + g1 * v1;
                    v2 = resx[(size_t)(r0+8) * N + col]     + g0 * v2;
                    v3 = resx[(size_t)(r0+8) * N + col + 1] + g1 * v3;
                }
                *(float2*)(Cf + (size_t)r0 * N + col)       = make_float2(v0, v1);
                *(float2*)(Cf + (size_t)(r0 + 8) * N + col) = make_float2(v2, v3);
            } else if (EPI == 2) {
                half* act = (half*)Cout;
                int oc = col >> 1;
                act[(size_t)r0 * FF + oc]       = __float2half(siluf(v0) * v1);
                act[(size_t)(r0 + 8) * FF + oc] = __float2half(siluf(v2) * v3);
            } else if (EPI == 3) {
                int l0 = r0 & 2047, l1 = (r0 + 8) & 2047;
                int sec = col >> 10, cc = col & 1023;
                int h = cc >> 6, d = cc & 63, p = d >> 1;
                int z = bb * H + h;
                if (sec < 2) {
                    float c0 = fc[l0*32+p], s0 = fs[l0*32+p];
                    float c1 = fc[l1*32+p], s1 = fs[l1*32+p];
                    float a0 = v0*c0 - v1*s0, b0 = v0*s0 + v1*c0;
                    float a1 = v2*c1 - v3*s1, b1 = v2*s1 + v3*c1;
                    half* dst;
                    if (sec == 0) { a0*=SCL; b0*=SCL; a1*=SCL; b1*=SCL; dst = (half*)Cout; }
                    else dst = khp;
                    *(half2*)(dst + ((size_t)z * L + l0) * 64 + d) = __floats2half2_rn(a0, b0);
                    *(half2*)(dst + ((size_t)z * L + l1) * 64 + d) = __floats2half2_rn(a1, b1);
                } else {
                    *(half2*)(vtp + ((size_t)z * L + l0) * 64 + d) = __floats2half2_rn(v0, v1);
                    *(half2*)(vtp + ((size_t)z * L + l1) * 64 + d) = __floats2half2_rn(v2, v3);
                }
            } else if (EPI == 4) {
                int l0 = r0 & 2047, l1 = (r0 + 8) & 2047;
                int h = col >> 6, d = col & 63;
                int z = bb * H + h;
                half* qh = (half*)Cout;
                *(half2*)(qh + ((size_t)z * L + l0) * 64 + d) = __floats2half2_rn(v0*SCL, v1*SCL);
                *(half2*)(qh + ((size_t)z * L + l1) * 64 + d) = __floats2half2_rn(v2*SCL, v3*SCL);
            } else if (EPI == 5) {
                int b2 = r0 >> 9;
                int k0 = r0 & 511, k1 = (r0 + 8) & 511;
                int sec = col >> 10, cc = col & 1023;
                int h = cc >> 6, d = cc & 63;
                int z = b2 * H + h;
                half* dst = (sec == 0) ? (half*)Cout : vtp;
                *(half2*)(dst + ((size_t)z * L2 + k0) * 64 + d) = __floats2half2_rn(v0, v1);
                *(half2*)(dst + ((size_t)z * L2 + k1) * 64 + d) = __floats2half2_rn(v2, v3);
            }
        }
    }
}

#define GSM (2 * STG)
template<int EPI>
static inline void launch_gmma(const half* A, const half* Bw, void* Co, int M, int N, int K,
                               const float* resx, const float* mods, const float* bias, int goff,
                               const float* fc, const float* fs, half* kh, half* vt, int Lk) {
    cudaFuncSetAttribute(gmma<EPI>, cudaFuncAttributeMaxDynamicSharedMemorySize, GSM);
    gmma<EPI><<<dim3(N/256, M/128), 256, GSM>>>(A, Bw, Co, M, N, K,
                                                resx, mods, bias, goff, fc, fs, kh, vt, Lk);
}

// ---- fused flash attention (V row-major, ldmatrix.trans for PV) ----
#define FA_SMEM 49152

__global__ void __launch_bounds__(256) fattn_kernel(
    const half* __restrict__ Qg, const half* __restrict__ Kg, const half* __restrict__ Vg,
    half* __restrict__ act, int Lk)
{
    extern __shared__ char smem[];
    uint32_t sb = smem_u32(smem);
    const uint32_t sQ = sb, sKV = sb + 16384;
    const int tid = threadIdx.x, lane = tid & 31, wid = tid >> 5;
    const int lrow = lane & 15, lch = lane >> 4;
    const int z = blockIdx.y;
    const int q0 = blockIdx.x << 7;
    const half* Qz = Qg + ((size_t)z * L + q0) * D;
    const half* Kz = Kg + (size_t)z * Lk * D;
    const half* Vz = Vg + (size_t)z * Lk * D;
    const uint32_t ONE2 = 0x3C003C00u;

    for (int id = tid; id < 1024; id += 256) {
        int row = id >> 3, c = id & 7;
        cp16(sQ + row * 128 + ((c ^ (row & 7)) << 4), Qz + row * D + c * 8);
    }
    auto load_kv = [&](int j, int buf) {
        uint32_t base = sKV + (uint32_t)buf * 16384;
        for (int id = tid; id < 1024; id += 256) {
            int row = (id >> 3) & 63, c = id & 7;
            const half* src = (id < 512) ? Kz : Vz;
            uint32_t off = (id < 512) ? 0u : 8192u;
            cp16(base + off + row * 128 + ((c ^ (row & 7)) << 4),
                 src + (size_t)(j * 64 + row) * D + c * 8);
        }
    };
    load_kv(0, 0);
    asm volatile("cp.async.commit_group;");
    const int nch = Lk >> 6;
    load_kv(1, 1);
    asm volatile("cp.async.commit_group;");

    float accO[8][4], accL[4];
#pragma unroll
    for (int n = 0; n < 8; n++)
#pragma unroll
        for (int v = 0; v < 4; v++) accO[n][v] = 0.f;
#pragma unroll
    for (int v = 0; v < 4; v++) accL[v] = 0.f;
    float m0 = -1e30f, m1 = -1e30f;
    uint32_t aq[4][4];

    for (int j = 0; j < nch; j++) {
        asm volatile("cp.async.wait_group 1;");
        __syncthreads();
        if (j == 0) {
#pragma unroll
            for (int ks = 0; ks < 4; ks++) {
                int row = (wid << 4) + lrow;
                int ch = (ks << 1) + lch;
                ldsm4(aq[ks], sQ + row * 128 + ((ch ^ (row & 7)) << 4));
            }
        }
        uint32_t bK = sKV + (uint32_t)(j & 1) * 16384;
        uint32_t bV = bK + 8192;

        float s[8][4];
#pragma unroll
        for (int n = 0; n < 8; n++)
#pragma unroll
            for (int v = 0; v < 4; v++) s[n][v] = 0.f;
#pragma unroll
        for (int ks = 0; ks < 4; ks++) {
            uint32_t b[4][4];
            int ch = (ks << 1) + lch;
#pragma unroll
            for (int p = 0; p < 4; p++) {
                int row = (p << 4) + lrow;
                ldsm4(b[p], bK + row * 128 + ((ch ^ (row & 7)) << 4));
            }
#pragma unroll
            for (int n = 0; n < 8; n++)
                mma16816(s[n], aq[ks], b[n >> 1][n & 1], b[n >> 1][2 + (n & 1)]);
        }

        float mt0 = -1e30f, mt1 = -1e30f;
#pragma unroll
        for (int n = 0; n < 8; n++) {
            mt0 = fmaxf(mt0, fmaxf(s[n][0], s[n][1]));
            mt1 = fmaxf(mt1, fmaxf(s[n][2], s[n][3]));
        }
        mt0 = fmaxf(mt0, __shfl_xor_sync(0xffffffff, mt0, 1));
        mt0 = fmaxf(mt0, __shfl_xor_sync(0xffffffff, mt0, 2));
        mt1 = fmaxf(mt1, __shfl_xor_sync(0xffffffff, mt1, 1));
        mt1 = fmaxf(mt1, __shfl_xor_sync(0xffffffff, mt1, 2));
        float M0 = fmaxf(m0, mt0), M1 = fmaxf(m1, mt1);
        float c0 = exp2f(m0 - M0), c1 = exp2f(m1 - M1);
        m0 = M0; m1 = M1;

        uint32_t pa[4][4];
#pragma unroll
        for (int t = 0; t < 4; t++) {
            pa[t][0] = ex2h2(s[2*t][0]   - M0, s[2*t][1]   - M0);
            pa[t][1] = ex2h2(s[2*t][2]   - M1, s[2*t][3]   - M1);
            pa[t][2] = ex2h2(s[2*t+1][0] - M0, s[2*t+1][1] - M0);
            pa[t][3] = ex2h2(s[2*t+1][2] - M1, s[2*t+1][3] - M1);
        }

#pragma unroll
        for (int n = 0; n < 8; n++) {
            accO[n][0] *= c0; accO[n][1] *= c0;
            accO[n][2] *= c1; accO[n][3] *= c1;
        }
        accL[0] *= c0; accL[2] *= c1;
#pragma unroll
        for (int kt = 0; kt < 4; kt++)
            mma16816(accL, pa[kt], ONE2, ONE2);

#pragma unroll
        for (int kt = 0; kt < 4; kt++) {
            uint32_t bt[4][4];
#pragma unroll
            for (int p = 0; p < 4; p++) {
                int row = (kt << 4) + lrow;
                int ch = (p << 1) + lch;
                ldsm4t(bt[p], bV + row * 128 + ((ch ^ (row & 7)) << 4));
            }
#pragma unroll
            for (int n = 0; n < 8; n++)
                mma16816(accO[n], pa[kt], bt[n >> 1][(n & 1) << 1], bt[n >> 1][((n & 1) << 1) + 1]);
        }

        __syncthreads();
        if (j + 2 < nch) load_kv(j + 2, j & 1);
        asm volatile("cp.async.commit_group;");
    }

    float inv0 = 1.f / accL[0], inv1 = 1.f / accL[2];
    int b = z >> 4, h = z & 15;
    int row0 = q0 + (wid << 4) + (lane >> 2);
    half* a0 = act + ((size_t)(b * L + row0) * C) + h * 64;
    half* a1 = a0 + (size_t)8 * C;
#pragma unroll
    for (int n = 0; n < 8; n++) {
        int col = (n << 3) + ((lane & 3) << 1);
        *(half2*)(a0 + col) = __floats2half2_rn(accO[n][0] * inv0, accO[n][1] * inv0);
        *(half2*)(a1 + col) = __floats2half2_rn(accO[n][2] * inv1, accO[n][3] * inv1);
    }
}

static inline void fattn(const half* Q, const half* K, const half* V, half* act, int Lk) {
    cudaFuncSetAttribute(fattn_kernel, cudaFuncAttributeMaxDynamicSharedMemorySize, FA_SMEM);
    fattn_kernel<<<dim3(L/128, ZB), 256, FA_SMEM>>>(Q, K, V, act, Lk);
}

// ---- merged weight convert ----
struct WJob { const float* W; half* T; int K, N, rs, ro, tile0; };
struct WAll { WJob j[9]; int ntiles; };

__global__ void wconvert_all_kernel(WAll wa) {
    __shared__ float t[32][33];
    int g = blockIdx.x;
    int ji = 0;
#pragma unroll
    for (int k = 1; k < 9; k++) if (g >= wa.j[k].tile0) ji = k;
    WJob w = wa.j[ji];
    int lt = g - w.tile0;
    int nx = w.N >> 5;
    int n0 = (lt % nx) << 5, k0 = (lt / nx) << 5;
    int tx = threadIdx.x, ty = threadIdx.y;
#pragma unroll
    for (int i = 0; i < 32; i += 8) t[ty + i][tx] = w.W[(size_t)(k0 + ty + i) * w.N + n0 + tx];
    __syncthreads();
#pragma unroll
    for (int i = 0; i < 32; i += 8)
        w.T[(size_t)((n0 + ty + i) * w.rs + w.ro) * w.K + k0 + tx] = __float2half(t[tx][ty + i]);
}

__global__ void silu2h_kernel(const float* __restrict__ in, half* __restrict__ o) {
    int i = blockIdx.x * blockDim.x + threadIdx.x;
    if (i >= 128 * C) return;
    o[i] = (i < B * C) ? __float2half(siluf(in[i])) : __float2half(0.f);
}
__global__ void aconvert_kernel(const float* __restrict__ a, half* __restrict__ o, size_t n) {
    size_t i = (size_t)blockIdx.x * blockDim.x + threadIdx.x;
    if (i >= n) return;
    o[i] = __float2half(a[i]);
}

__global__ void rmsnorm_kernel(const float* __restrict__ x, const float* __restrict__ w,
                               const float* __restrict__ mods, const float* __restrict__ bias,
                               int sh_off, int sc_off, half* __restrict__ o) {
    int row = blockIdx.x, b = row / L;
    const float4* xr = (const float4*)(x + (size_t)row * C);
    float4 v = xr[threadIdx.x];
    float s = v.x*v.x + v.y*v.y + v.z*v.z + v.w*v.w;
    __shared__ float red[8];
#pragma unroll
    for (int o2 = 16; o2 > 0; o2 >>= 1) s += __shfl_xor_sync(0xffffffff, s, o2);
    if ((threadIdx.x & 31) == 0) red[threadIdx.x >> 5] = s;
    __syncthreads();
    s = red[threadIdx.x & 7];
#pragma unroll
    for (int o2 = 4; o2 > 0; o2 >>= 1) s += __shfl_xor_sync(0xffffffff, s, o2);
    float inv = rsqrtf(s / (float)C + EPS);
    int c = threadIdx.x << 2;
    float4 wv = *(const float4*)(w + c);
    float r[4] = {v.x * inv * wv.x, v.y * inv * wv.y, v.z * inv * wv.z, v.w * inv * wv.w};
    if (mods) {
        float4 sc = *(const float4*)(mods + (size_t)b * 6 * C + sc_off + c);
        float4 scb = *(const float4*)(bias + sc_off + c);
        float4 sh = *(const float4*)(mods + (size_t)b * 6 * C + sh_off + c);
        float4 shb = *(const float4*)(bias + sh_off + c);
        r[0] = r[0] * (1.f + sc.x + scb.x) + sh.x + shb.x;
        r[1] = r[1] * (1.f + sc.y + scb.y) + sh.y + shb.y;
        r[2] = r[2] * (1.f + sc.z + scb.z) + sh.z + shb.z;
        r[3] = r[3] * (1.f + sc.w + scb.w) + sh.w + shb.w;
    }
    half2 h0 = __floats2half2_rn(r[0], r[1]);
    half2 h1 = __floats2half2_rn(r[2], r[3]);
    uint2 pk = { *(uint32_t*)&h0, *(uint32_t*)&h1 };
    *(uint2*)(o + (size_t)row * C + c) = pk;
}

// ---- launch ----
#define GSYM(p, s) cudaGetSymbolAddress((void**)&p, s)
extern "C" void kernel_launch(void* const* d_in, const int* in_sizes, int n_in,
                              void* d_out, int out_size) {
    const float* x     = (const float*)d_in[0];
    const float* t_mod = (const float*)d_in[1];
    const float* audio = (const float*)d_in[2];
    const float* fcos  = (const float*)d_in[3];
    const float* fsin  = (const float*)d_in[4];
    const float* n1w   = (const float*)d_in[5];
    const float* n2w   = (const float*)d_in[6];
    const float* n3w   = (const float*)d_in[7];
    const float* Wqkv  = (const float*)d_in[8];
    const float* Wsa   = (const float*)d_in[9];
    const float* Wq    = (const float*)d_in[10];
    const float* Wkv   = (const float*)d_in[11];
    const float* Wca   = (const float*)d_in[12];
    const float* Wg    = (const float*)d_in[13];
    const float* Wu    = (const float*)d_in[14];
    const float* Wd    = (const float*)d_in[15];
    const float* adaW  = (const float*)d_in[16];
    const float* adaB  = (const float*)d_in[17];
    float* out = (float*)d_out;

    float *mods_p, *x_p;
    half *hid, *act, *ctx, *sm, *qh_p, *kh_p, *v_p;
    half *qkvw, *saw, *qw, *kvw, *caw, *guw, *dw, *adw;
    GSYM(mods_p, g_mods); GSYM(x_p, g_x);
    GSYM(hid, g_h); GSYM(act, g_act); GSYM(ctx, g_ctx); GSYM(sm, g_sm);
    GSYM(qh_p, g_qh); GSYM(kh_p, g_kh); GSYM(v_p, g_v);
    GSYM(qkvw, w_qkv); GSYM(saw, w_sa); GSYM(qw, w_q); GSYM(kvw, w_kv);
    GSYM(caw, w_ca); GSYM(guw, w_gu); GSYM(dw, w_d); GSYM(adw, w_ada);

    WAll wa;
    const float* Ws[9] = {Wqkv, Wsa, Wq, Wkv, Wca, Wg, Wu, Wd, adaW};
    half* Ts[9] = {qkvw, saw, qw, kvw, caw, guw, guw, dw, adw};
    int Ks[9] = {C, C, C, TD, C, C, C, FF, C};
    int Ns[9] = {3*C, C, C, 2*C, C, FF, FF, C, 6*C};
    int Rs[9] = {1, 1, 1, 1, 1, 2, 2, 1, 1};
    int Ro[9] = {0, 0, 0, 0, 0, 0, 1, 0, 0};
    int tile = 0;
    for (int i = 0; i < 9; i++) {
        wa.j[i] = {Ws[i], Ts[i], Ks[i], Ns[i], Rs[i], Ro[i], tile};
        tile += (Ks[i] >> 5) * (Ns[i] >> 5);
    }
    wa.ntiles = tile;
    wconvert_all_kernel<<<tile, dim3(32, 8)>>>(wa);

    // adaLN (M padded to 128; bias folded at consumers)
    silu2h_kernel<<<(128*C + 255)/256, 256>>>(t_mod, sm);
    launch_gmma<0>(sm, adw, mods_p, 128, 6*C, C,
                   nullptr, nullptr, nullptr, 0, nullptr, nullptr, nullptr, nullptr, 0);

    // ---- self-attention ----
    rmsnorm_kernel<<<BL, 256>>>(x, n1w, mods_p, adaB, 0, C, act);
    launch_gmma<3>(act, qkvw, qh_p, BL, 3*C, C,
                   nullptr, nullptr, nullptr, 0, fcos, fsin, kh_p, v_p, L);
    fattn(qh_p, kh_p, v_p, act, L);
    launch_gmma<0>(act, saw, x_p, BL, C, C,
                   x, mods_p, adaB, 2*C, nullptr, nullptr, nullptr, nullptr, 0);

    // ---- cross-attention ----
    rmsnorm_kernel<<<BL, 256>>>(x_p, n2w, nullptr, nullptr, 0, 0, act);
    launch_gmma<4>(act, qw, qh_p, BL, C, C,
                   nullptr, nullptr, nullptr, 0, nullptr, nullptr, nullptr, nullptr, L);
    aconvert_kernel<<<(BL2*TD + 255)/256, 256>>>(audio, ctx, (size_t)BL2*TD);
    launch_gmma<5>(ctx, kvw, kh_p, BL2, 2*C, TD,
                   nullptr, nullptr, nullptr, 0, nullptr, nullptr, nullptr, v_p, L2);
    fattn(qh_p, kh_p, v_p, act, L2);
    launch_gmma<0>(act, caw, x_p, BL, C, C,
                   x_p, nullptr, nullptr, 0, nullptr, nullptr, nullptr, nullptr, 0);

    // ---- MLP ----
    rmsnorm_kernel<<<BL, 256>>>(x_p, n3w, mods_p, adaB, 3*C, 4*C, act);
    launch_gmma<2>(act, guw, hid, BL, 2*FF, C,
                   nullptr, nullptr, nullptr, 0, nullptr, nullptr, nullptr, nullptr, 0);
    launch_gmma<0>(hid, dw, out, BL, C, FF,
                   x_p, mods_p, adaB, 5*C, nullptr, nullptr, nullptr, nullptr, 0);
}

// round 16
// speedup vs baseline: 1.5052x; 1.5052x over previous
#include <cuda_runtime.h>
#include <cuda_fp16.h>
#include <stdint.h>

#define B 2
#define L 2048
#define C 1024
#define H 16
#define D 64
#define L2 512
#define TD 768
#define FF 4096
#define EPS 1e-6f
#define BL 4096
#define BL2 1024
#define ZB 32
#define SCL 0.180336880f   // 0.125 * log2(e)

// ---- scratch ----
__device__ float g_mods[128 * 6 * C];
__device__ float g_x[BL * C];
__device__ half g_h[(size_t)BL * FF];
__device__ half g_act[(size_t)BL * C];
__device__ half g_ctx[BL2 * TD];
__device__ half g_sm[128 * C];
__device__ half g_qh[(size_t)ZB * L * D];
__device__ half g_kh[(size_t)ZB * L * D];
__device__ half g_v[(size_t)ZB * L * D];
// weights fp16, transposed [N][K]
__device__ half w_qkv[3*C*C];
__device__ half w_sa[C*C];
__device__ half w_q[C*C];
__device__ half w_kv[2*C*TD];
__device__ half w_ca[C*C];
__device__ half w_gu[(size_t)2*FF*C];
__device__ half w_d[(size_t)FF*C];
__device__ half w_ada[6*C*C];

// ---- helpers ----
__device__ __forceinline__ uint32_t smem_u32(const void* p) {
    uint32_t a;
    asm("{ .reg .u64 t; cvta.to.shared.u64 t, %1; cvt.u32.u64 %0, t; }" : "=r"(a) : "l"(p));
    return a;
}
__device__ __forceinline__ void cp16(uint32_t s, const void* g) {
    asm volatile("cp.async.cg.shared.global [%0], [%1], 16;" :: "r"(s), "l"(g));
}
__device__ __forceinline__ void ldsm4(uint32_t* r, uint32_t a) {
    asm volatile("ldmatrix.sync.aligned.m8n8.x4.shared.b16 {%0,%1,%2,%3}, [%4];"
        : "=r"(r[0]), "=r"(r[1]), "=r"(r[2]), "=r"(r[3]) : "r"(a));
}
__device__ __forceinline__ void ldsm4t(uint32_t* r, uint32_t a) {
    asm volatile("ldmatrix.sync.aligned.m8n8.x4.trans.shared.b16 {%0,%1,%2,%3}, [%4];"
        : "=r"(r[0]), "=r"(r[1]), "=r"(r[2]), "=r"(r[3]) : "r"(a));
}
__device__ __forceinline__ void mma16816(float* d, const uint32_t* a, uint32_t b0, uint32_t b1) {
    asm volatile("mma.sync.aligned.m16n8k16.row.col.f32.f16.f16.f32 "
        "{%0,%1,%2,%3}, {%4,%5,%6,%7}, {%8,%9}, {%0,%1,%2,%3};"
        : "+f"(d[0]), "+f"(d[1]), "+f"(d[2]), "+f"(d[3])
        : "r"(a[0]), "r"(a[1]), "r"(a[2]), "r"(a[3]), "r"(b0), "r"(b1));
}
__device__ __forceinline__ uint32_t ex2h2(float a, float b) {
    uint32_t h;
    asm("{ .reg .b32 t;\n\t"
        "cvt.rn.f16x2.f32 t, %2, %1;\n\t"
        "ex2.approx.f16x2 %0, t; }"
        : "=r"(h) : "f"(a), "f"(b));
    return h;
}
__device__ __forceinline__ float siluf(float v) { return v / (1.f + __expf(-v)); }

// ---- pipelined fp16 mma GEMM, K-chunk 64, 4-stage, fused epilogues ----
// EPI: 0 = float out (+ optional residual x + gate*acc)
//      2 = swiglu (interleaved gate/up) -> half [M][FF]
//      3 = SA qkv: rope q,k -> qh,kh; v row-major
//      4 = CA q   5 = CA kv
#define NSTAGE 4
#define STG 49152     // A 16K | B 32K

template<int EPI>
__global__ void __launch_bounds__(256) gmma(
    const half* __restrict__ Ax, const half* __restrict__ B0,
    void* __restrict__ Cout, int M, int N, int K,
    const float* __restrict__ resx, const float* __restrict__ mods,
    const float* __restrict__ bias, int goff,
    const float* __restrict__ fc, const float* __restrict__ fs,
    half* __restrict__ khp, half* __restrict__ vtp, int Lk)
{
    extern __shared__ char smem[];
    uint32_t sb = smem_u32(smem);
    const int tid = threadIdx.x, lane = tid & 31, wid = tid >> 5;
    const int wm = (wid & 1) << 6;
    const int wn = (wid >> 1) << 6;
    const int tM = blockIdx.y << 7, tN = blockIdx.x << 8;

    float acc[4][8][4];
#pragma unroll
    for (int f = 0; f < 4; f++)
#pragma unroll
        for (int n = 0; n < 8; n++)
#pragma unroll
            for (int v = 0; v < 4; v++) acc[f][n][v] = 0.f;

    const int kIters = K >> 6;

    auto load_stage = [&](int s, int k0) {
#pragma unroll
        for (int i = 0; i < 12; i++) {
            int id = tid + (i << 8);
            const half* g; uint32_t dst;
            if (id < 1024) {
                int row = id >> 3, c = id & 7;
                g = Ax + (size_t)(tM + row) * K + k0 + (c << 3);
                dst = sb + s * STG + row * 128 + ((c ^ (row & 7)) << 4);
            } else {
                int a = id - 1024;
                int row = a >> 3, c = a & 7;
                g = B0 + (size_t)(tN + row) * K + k0 + (c << 3);
                dst = sb + s * STG + 16384 + row * 128 + ((c ^ (row & 7)) << 4);
            }
            cp16(dst, g);
        }
    };

    for (int s = 0; s < NSTAGE - 1; s++) {
        load_stage(s, s << 6);
        asm volatile("cp.async.commit_group;");
    }

    const int lrow = lane & 15, lch = lane >> 4;

    for (int it = 0; it < kIters; it++) {
        asm volatile("cp.async.wait_group 2;");
        __syncthreads();
        if (it + NSTAGE - 1 < kIters)
            load_stage((it + NSTAGE - 1) % NSTAGE, (it + NSTAGE - 1) << 6);
        asm volatile("cp.async.commit_group;");

        uint32_t stg = sb + (uint32_t)(it % NSTAGE) * STG;
#pragma unroll
        for (int ks = 0; ks < 4; ks++) {
            int ch = (ks << 1) + lch;
            uint32_t a[4][4], b[4][4];
#pragma unroll
            for (int f = 0; f < 4; f++) {
                int row = wm + (f << 4) + lrow;
                ldsm4(a[f], stg + row * 128 + ((ch ^ (row & 7)) << 4));
            }
#pragma unroll
            for (int p = 0; p < 4; p++) {
                int row = wn + (p << 4) + lrow;
                ldsm4(b[p], stg + 16384u + row * 128 + ((ch ^ (row & 7)) << 4));
            }
#pragma unroll
            for (int f = 0; f < 4; f++)
#pragma unroll
                for (int n = 0; n < 8; n++)
                    mma16816(acc[f][n], a[f], b[n >> 1][n & 1], b[n >> 1][2 + (n & 1)]);
        }
    }

    const int bb = (EPI == 5) ? 0 : (tM >> 11);
#pragma unroll
    for (int f = 0; f < 4; f++) {
        int r0 = tM + wm + (f << 4) + (lane >> 2);
#pragma unroll
        for (int n = 0; n < 8; n++) {
            int col = tN + wn + (n << 3) + ((lane & 3) << 1);
            float v0 = acc[f][n][0], v1 = acc[f][n][1];
            float v2 = acc[f][n][2], v3 = acc[f][n][3];
            if (EPI == 0) {
                float* Cf = (float*)Cout;
                if (resx) {
                    float g0 = 1.f, g1 = 1.f;
                    if (mods) {
                        g0 = mods[(size_t)bb * 6 * C + goff + col]     + bias[goff + col];
                        g1 = mods[(size_t)bb * 6 * C + goff + col + 1] + bias[goff + col + 1];
                    }
                    v0 = resx[(size_t)r0 * N + col]         + g0 * v0;
                    v1 = resx[(size_t)r0 * N + col + 1]     + g1 * v1;
                    v2 = resx[(size_t)(r0+8) * N + col]     + g0 * v2;
                    v3 = resx[(size_t)(r0+8) * N + col + 1] + g1 * v3;
                }
                *(float2*)(Cf + (size_t)r0 * N + col)       = make_float2(v0, v1);
                *(float2*)(Cf + (size_t)(r0 + 8) * N + col) = make_float2(v2, v3);
            } else if (EPI == 2) {
                half* act = (half*)Cout;
                int oc = col >> 1;
                act[(size_t)r0 * FF + oc]       = __float2half(siluf(v0) * v1);
                act[(size_t)(r0 + 8) * FF + oc] = __float2half(siluf(v2) * v3);
            } else if (EPI == 3) {
                int l0 = r0 & 2047, l1 = (r0 + 8) & 2047;
                int sec = col >> 10, cc = col & 1023;
                int h = cc >> 6, d = cc & 63, p = d >> 1;
                int z = bb * H + h;
                if (sec < 2) {
                    float c0 = fc[l0*32+p], s0 = fs[l0*32+p];
                    float c1 = fc[l1*32+p], s1 = fs[l1*32+p];
                    float a0 = v0*c0 - v1*s0, b0 = v0*s0 + v1*c0;
                    float a1 = v2*c1 - v3*s1, b1 = v2*s1 + v3*c1;
                    half* dst;
                    if (sec == 0) { a0*=SCL; b0*=SCL; a1*=SCL; b1*=SCL; dst = (half*)Cout; }
                    else dst = khp;
                    *(half2*)(dst + ((size_t)z * L + l0) * 64 + d) = __floats2half2_rn(a0, b0);
                    *(half2*)(dst + ((size_t)z * L + l1) * 64 + d) = __floats2half2_rn(a1, b1);
                } else {
                    *(half2*)(vtp + ((size_t)z * L + l0) * 64 + d) = __floats2half2_rn(v0, v1);
                    *(half2*)(vtp + ((size_t)z * L + l1) * 64 + d) = __floats2half2_rn(v2, v3);
                }
            } else if (EPI == 4) {
                int l0 = r0 & 2047, l1 = (r0 + 8) & 2047;
                int h = col >> 6, d = col & 63;
                int z = bb * H + h;
                half* qh = (half*)Cout;
                *(half2*)(qh + ((size_t)z * L + l0) * 64 + d) = __floats2half2_rn(v0*SCL, v1*SCL);
                *(half2*)(qh + ((size_t)z * L + l1) * 64 + d) = __floats2half2_rn(v2*SCL, v3*SCL);
            } else if (EPI == 5) {
                int b2 = r0 >> 9;
                int k0 = r0 & 511, k1 = (r0 + 8) & 511;
                int sec = col >> 10, cc = col & 1023;
                int h = cc >> 6, d = cc & 63;
                int z = b2 * H + h;
                half* dst = (sec == 0) ? (half*)Cout : vtp;
                *(half2*)(dst + ((size_t)z * L2 + k0) * 64 + d) = __floats2half2_rn(v0, v1);
                *(half2*)(dst + ((size_t)z * L2 + k1) * 64 + d) = __floats2half2_rn(v2, v3);
            }
        }
    }
}

#define GSM (NSTAGE * STG)
template<int EPI>
static inline void launch_gmma(const half* A, const half* Bw, void* Co, int M, int N, int K,
                               const float* resx, const float* mods, const float* bias, int goff,
                               const float* fc, const float* fs, half* kh, half* vt, int Lk) {
    cudaFuncSetAttribute(gmma<EPI>, cudaFuncAttributeMaxDynamicSharedMemorySize, GSM);
    gmma<EPI><<<dim3(N/256, M/128), 256, GSM>>>(A, Bw, Co, M, N, K,
                                                resx, mods, bias, goff, fc, fs, kh, vt, Lk);
}

// ---- fused flash attention (V row-major, ldmatrix.trans for PV) ----
#define FA_SMEM 49152

__global__ void __launch_bounds__(256) fattn_kernel(
    const half* __restrict__ Qg, const half* __restrict__ Kg, const half* __restrict__ Vg,
    half* __restrict__ act, int Lk)
{
    extern __shared__ char smem[];
    uint32_t sb = smem_u32(smem);
    const uint32_t sQ = sb, sKV = sb + 16384;
    const int tid = threadIdx.x, lane = tid & 31, wid = tid >> 5;
    const int lrow = lane & 15, lch = lane >> 4;
    const int z = blockIdx.y;
    const int q0 = blockIdx.x << 7;
    const half* Qz = Qg + ((size_t)z * L + q0) * D;
    const half* Kz = Kg + (size_t)z * Lk * D;
    const half* Vz = Vg + (size_t)z * Lk * D;
    const uint32_t ONE2 = 0x3C003C00u;

    for (int id = tid; id < 1024; id += 256) {
        int row = id >> 3, c = id & 7;
        cp16(sQ + row * 128 + ((c ^ (row & 7)) << 4), Qz + row * D + c * 8);
    }
    auto load_kv = [&](int j, int buf) {
        uint32_t base = sKV + (uint32_t)buf * 16384;
        for (int id = tid; id < 1024; id += 256) {
            int row = (id >> 3) & 63, c = id & 7;
            const half* src = (id < 512) ? Kz : Vz;
            uint32_t off = (id < 512) ? 0u : 8192u;
            cp16(base + off + row * 128 + ((c ^ (row & 7)) << 4),
                 src + (size_t)(j * 64 + row) * D + c * 8);
        }
    };
    load_kv(0, 0);
    asm volatile("cp.async.commit_group;");
    const int nch = Lk >> 6;
    load_kv(1, 1);
    asm volatile("cp.async.commit_group;");

    float accO[8][4], accL[4];
#pragma unroll
    for (int n = 0; n < 8; n++)
#pragma unroll
        for (int v = 0; v < 4; v++) accO[n][v] = 0.f;
#pragma unroll
    for (int v = 0; v < 4; v++) accL[v] = 0.f;
    float m0 = -1e30f, m1 = -1e30f;
    uint32_t aq[4][4];

    for (int j = 0; j < nch; j++) {
        asm volatile("cp.async.wait_group 1;");
        __syncthreads();
        if (j == 0) {
#pragma unroll
            for (int ks = 0; ks < 4; ks++) {
                int row = (wid << 4) + lrow;
                int ch = (ks << 1) + lch;
                ldsm4(aq[ks], sQ + row * 128 + ((ch ^ (row & 7)) << 4));
            }
        }
        uint32_t bK = sKV + (uint32_t)(j & 1) * 16384;
        uint32_t bV = bK + 8192;

        float s[8][4];
#pragma unroll
        for (int n = 0; n < 8; n++)
#pragma unroll
            for (int v = 0; v < 4; v++) s[n][v] = 0.f;
#pragma unroll
        for (int ks = 0; ks < 4; ks++) {
            uint32_t b[4][4];
            int ch = (ks << 1) + lch;
#pragma unroll
            for (int p = 0; p < 4; p++) {
                int row = (p << 4) + lrow;
                ldsm4(b[p], bK + row * 128 + ((ch ^ (row & 7)) << 4));
            }
#pragma unroll
            for (int n = 0; n < 8; n++)
                mma16816(s[n], aq[ks], b[n >> 1][n & 1], b[n >> 1][2 + (n & 1)]);
        }

        float mt0 = -1e30f, mt1 = -1e30f;
#pragma unroll
        for (int n = 0; n < 8; n++) {
            mt0 = fmaxf(mt0, fmaxf(s[n][0], s[n][1]));
            mt1 = fmaxf(mt1, fmaxf(s[n][2], s[n][3]));
        }
        mt0 = fmaxf(mt0, __shfl_xor_sync(0xffffffff, mt0, 1));
        mt0 = fmaxf(mt0, __shfl_xor_sync(0xffffffff, mt0, 2));
        mt1 = fmaxf(mt1, __shfl_xor_sync(0xffffffff, mt1, 1));
        mt1 = fmaxf(mt1, __shfl_xor_sync(0xffffffff, mt1, 2));
        float M0 = fmaxf(m0, mt0), M1 = fmaxf(m1, mt1);
        float c0 = exp2f(m0 - M0), c1 = exp2f(m1 - M1);
        m0 = M0; m1 = M1;

        uint32_t pa[4][4];
#pragma unroll
        for (int t = 0; t < 4; t++) {
            pa[t][0] = ex2h2(s[2*t][0]   - M0, s[2*t][1]   - M0);
            pa[t][1] = ex2h2(s[2*t][2]   - M1, s[2*t][3]   - M1);
            pa[t][2] = ex2h2(s[2*t+1][0] - M0, s[2*t+1][1] - M0);
            pa[t][3] = ex2h2(s[2*t+1][2] - M1, s[2*t+1][3] - M1);
        }

#pragma unroll
        for (int n = 0; n < 8; n++) {
            accO[n][0] *= c0; accO[n][1] *= c0;
            accO[n][2] *= c1; accO[n][3] *= c1;
        }
        accL[0] *= c0; accL[2] *= c1;
#pragma unroll
        for (int kt = 0; kt < 4; kt++)
            mma16816(accL, pa[kt], ONE2, ONE2);

#pragma unroll
        for (int kt = 0; kt < 4; kt++) {
            uint32_t bt[4][4];
#pragma unroll
            for (int p = 0; p < 4; p++) {
                int row = (kt << 4) + lrow;
                int ch = (p << 1) + lch;
                ldsm4t(bt[p], bV + row * 128 + ((ch ^ (row & 7)) << 4));
            }
#pragma unroll
            for (int n = 0; n < 8; n++)
                mma16816(accO[n], pa[kt], bt[n >> 1][(n & 1) << 1], bt[n >> 1][((n & 1) << 1) + 1]);
        }

        __syncthreads();
        if (j + 2 < nch) load_kv(j + 2, j & 1);
        asm volatile("cp.async.commit_group;");
    }

    float inv0 = 1.f / accL[0], inv1 = 1.f / accL[2];
    int b = z >> 4, h = z & 15;
    int row0 = q0 + (wid << 4) + (lane >> 2);
    half* a0 = act + ((size_t)(b * L + row0) * C) + h * 64;
    half* a1 = a0 + (size_t)8 * C;
#pragma unroll
    for (int n = 0; n < 8; n++) {
        int col = (n << 3) + ((lane & 3) << 1);
        *(half2*)(a0 + col) = __floats2half2_rn(accO[n][0] * inv0, accO[n][1] * inv0);
        *(half2*)(a1 + col) = __floats2half2_rn(accO[n][2] * inv1, accO[n][3] * inv1);
    }
}

static inline void fattn(const half* Q, const half* K, const half* V, half* act, int Lk) {
    cudaFuncSetAttribute(fattn_kernel, cudaFuncAttributeMaxDynamicSharedMemorySize, FA_SMEM);
    fattn_kernel<<<dim3(L/128, ZB), 256, FA_SMEM>>>(Q, K, V, act, Lk);
}

// ---- merged weight convert ----
struct WJob { const float* W; half* T; int K, N, rs, ro, tile0; };
struct WAll { WJob j[9]; int ntiles; };

__global__ void wconvert_all_kernel(WAll wa) {
    __shared__ float t[32][33];
    int g = blockIdx.x;
    int ji = 0;
#pragma unroll
    for (int k = 1; k < 9; k++) if (g >= wa.j[k].tile0) ji = k;
    WJob w = wa.j[ji];
    int lt = g - w.tile0;
    int nx = w.N >> 5;
    int n0 = (lt % nx) << 5, k0 = (lt / nx) << 5;
    int tx = threadIdx.x, ty = threadIdx.y;
#pragma unroll
    for (int i = 0; i < 32; i += 8) t[ty + i][tx] = w.W[(size_t)(k0 + ty + i) * w.N + n0 + tx];
    __syncthreads();
#pragma unroll
    for (int i = 0; i < 32; i += 8)
        w.T[(size_t)((n0 + ty + i) * w.rs + w.ro) * w.K + k0 + tx] = __float2half(t[tx][ty + i]);
}

__global__ void silu2h_kernel(const float* __restrict__ in, half* __restrict__ o) {
    int i = blockIdx.x * blockDim.x + threadIdx.x;
    if (i >= 128 * C) return;
    o[i] = (i < B * C) ? __float2half(siluf(in[i])) : __float2half(0.f);
}
__global__ void aconvert_kernel(const float* __restrict__ a, half* __restrict__ o, size_t n) {
    size_t i = (size_t)blockIdx.x * blockDim.x + threadIdx.x;
    if (i >= n) return;
    o[i] = __float2half(a[i]);
}

__global__ void rmsnorm_kernel(const float* __restrict__ x, const float* __restrict__ w,
                               const float* __restrict__ mods, const float* __restrict__ bias,
                               int sh_off, int sc_off, half* __restrict__ o) {
    int row = blockIdx.x, b = row / L;
    const float4* xr = (const float4*)(x + (size_t)row * C);
    float4 v = xr[threadIdx.x];
    float s = v.x*v.x + v.y*v.y + v.z*v.z + v.w*v.w;
    __shared__ float red[8];
#pragma unroll
    for (int o2 = 16; o2 > 0; o2 >>= 1) s += __shfl_xor_sync(0xffffffff, s, o2);
    if ((threadIdx.x & 31) == 0) red[threadIdx.x >> 5] = s;
    __syncthreads();
    s = red[threadIdx.x & 7];
#pragma unroll
    for (int o2 = 4; o2 > 0; o2 >>= 1) s += __shfl_xor_sync(0xffffffff, s, o2);
    float inv = rsqrtf(s / (float)C + EPS);
    int c = threadIdx.x << 2;
    float4 wv = *(const float4*)(w + c);
    float r[4] = {v.x * inv * wv.x, v.y * inv * wv.y, v.z * inv * wv.z, v.w * inv * wv.w};
    if (mods) {
        float4 sc = *(const float4*)(mods + (size_t)b * 6 * C + sc_off + c);
        float4 scb = *(const float4*)(bias + sc_off + c);
        float4 sh = *(const float4*)(mods + (size_t)b * 6 * C + sh_off + c);
        float4 shb = *(const float4*)(bias + sh_off + c);
        r[0] = r[0] * (1.f + sc.x + scb.x) + sh.x + shb.x;
        r[1] = r[1] * (1.f + sc.y + scb.y) + sh.y + shb.y;
        r[2] = r[2] * (1.f + sc.z + scb.z) + sh.z + shb.z;
        r[3] = r[3] * (1.f + sc.w + scb.w) + sh.w + shb.w;
    }
    half2 h0 = __floats2half2_rn(r[0], r[1]);
    half2 h1 = __floats2half2_rn(r[2], r[3]);
    uint2 pk = { *(uint32_t*)&h0, *(uint32_t*)&h1 };
    *(uint2*)(o + (size_t)row * C + c) = pk;
}

// ---- launch ----
#define GSYM(p, s) cudaGetSymbolAddress((void**)&p, s)
extern "C" void kernel_launch(void* const* d_in, const int* in_sizes, int n_in,
                              void* d_out, int out_size) {
    const float* x     = (const float*)d_in[0];
    const float* t_mod = (const float*)d_in[1];
    const float* audio = (const float*)d_in[2];
    const float* fcos  = (const float*)d_in[3];
    const float* fsin  = (const float*)d_in[4];
    const float* n1w   = (const float*)d_in[5];
    const float* n2w   = (const float*)d_in[6];
    const float* n3w   = (const float*)d_in[7];
    const float* Wqkv  = (const float*)d_in[8];
    const float* Wsa   = (const float*)d_in[9];
    const float* Wq    = (const float*)d_in[10];
    const float* Wkv   = (const float*)d_in[11];
    const float* Wca   = (const float*)d_in[12];
    const float* Wg    = (const float*)d_in[13];
    const float* Wu    = (const float*)d_in[14];
    const float* Wd    = (const float*)d_in[15];
    const float* adaW  = (const float*)d_in[16];
    const float* adaB  = (const float*)d_in[17];
    float* out = (float*)d_out;

    float *mods_p, *x_p;
    half *hid, *act, *ctx, *sm, *qh_p, *kh_p, *v_p;
    half *qkvw, *saw, *qw, *kvw, *caw, *guw, *dw, *adw;
    GSYM(mods_p, g_mods); GSYM(x_p, g_x);
    GSYM(hid, g_h); GSYM(act, g_act); GSYM(ctx, g_ctx); GSYM(sm, g_sm);
    GSYM(qh_p, g_qh); GSYM(kh_p, g_kh); GSYM(v_p, g_v);
    GSYM(qkvw, w_qkv); GSYM(saw, w_sa); GSYM(qw, w_q); GSYM(kvw, w_kv);
    GSYM(caw, w_ca); GSYM(guw, w_gu); GSYM(dw, w_d); GSYM(adw, w_ada);

    WAll wa;
    const float* Ws[9] = {Wqkv, Wsa, Wq, Wkv, Wca, Wg, Wu, Wd, adaW};
    half* Ts[9] = {qkvw, saw, qw, kvw, caw, guw, guw, dw, adw};
    int Ks[9] = {C, C, C, TD, C, C, C, FF, C};
    int Ns[9] = {3*C, C, C, 2*C, C, FF, FF, C, 6*C};
    int Rs[9] = {1, 1, 1, 1, 1, 2, 2, 1, 1};
    int Ro[9] = {0, 0, 0, 0, 0, 0, 1, 0, 0};
    int tile = 0;
    for (int i = 0; i < 9; i++) {
        wa.j[i] = {Ws[i], Ts[i], Ks[i], Ns[i], Rs[i], Ro[i], tile};
        tile += (Ks[i] >> 5) * (Ns[i] >> 5);
    }
    wa.ntiles = tile;
    wconvert_all_kernel<<<tile, dim3(32, 8)>>>(wa);

    // adaLN (M padded to 128; bias folded at consumers)
    silu2h_kernel<<<(128*C + 255)/256, 256>>>(t_mod, sm);
    launch_gmma<0>(sm, adw, mods_p, 128, 6*C, C,
                   nullptr, nullptr, nullptr, 0, nullptr, nullptr, nullptr, nullptr, 0);

    // ---- self-attention ----
    rmsnorm_kernel<<<BL, 256>>>(x, n1w, mods_p, adaB, 0, C, act);
    launch_gmma<3>(act, qkvw, qh_p, BL, 3*C, C,
                   nullptr, nullptr, nullptr, 0, fcos, fsin, kh_p, v_p, L);
    fattn(qh_p, kh_p, v_p, act, L);
    launch_gmma<0>(act, saw, x_p, BL, C, C,
                   x, mods_p, adaB, 2*C, nullptr, nullptr, nullptr, nullptr, 0);

    // ---- cross-attention ----
    rmsnorm_kernel<<<BL, 256>>>(x_p, n2w, nullptr, nullptr, 0, 0, act);
    launch_gmma<4>(act, qw, qh_p, BL, C, C,
                   nullptr, nullptr, nullptr, 0, nullptr, nullptr, nullptr, nullptr, L);
    aconvert_kernel<<<(BL2*TD + 255)/256, 256>>>(audio, ctx, (size_t)BL2*TD);
    launch_gmma<5>(ctx, kvw, kh_p, BL2, 2*C, TD,
                   nullptr, nullptr, nullptr, 0, nullptr, nullptr, nullptr, v_p, L2);
    fattn(qh_p, kh_p, v_p, act, L2);
    launch_gmma<0>(act, caw, x_p, BL, C, C,
                   x_p, nullptr, nullptr, 0, nullptr, nullptr, nullptr, nullptr, 0);

    // ---- MLP ----
    rmsnorm_kernel<<<BL, 256>>>(x_p, n3w, mods_p, adaB, 3*C, 4*C, act);
    launch_gmma<2>(act, guw, hid, BL, 2*FF, C,
                   nullptr, nullptr, nullptr, 0, nullptr, nullptr, nullptr, nullptr, 0);
    launch_gmma<0>(hid, dw, out, BL, C, FF,
                   x_p, mods_p, adaB, 5*C, nullptr, nullptr, nullptr, nullptr, 0);
}

// round 17
// speedup vs baseline: 1.5066x; 1.0009x over previous
#include <cuda_runtime.h>
#include <cuda_fp16.h>
#include <stdint.h>

#define B 2
#define L 2048
#define C 1024
#define H 16
#define D 64
#define L2 512
#define TD 768
#define FF 4096
#define EPS 1e-6f
#define BL 4096
#define BL2 1024
#define ZB 32
#define SCL 0.180336880f   // 0.125 * log2(e)

// ---- scratch ----
__device__ float g_mods[128 * 6 * C];
__device__ float g_x[BL * C];
__device__ half g_h[(size_t)BL * FF];
__device__ half g_act[(size_t)BL * C];
__device__ half g_ctx[BL2 * TD];
__device__ half g_sm[128 * C];
__device__ half g_qh[(size_t)ZB * L * D];
__device__ half g_kh[(size_t)ZB * L * D];
__device__ half g_v[(size_t)ZB * L * D];
// weights fp16, transposed [N][K]
__device__ half w_qkv[3*C*C];
__device__ half w_sa[C*C];
__device__ half w_q[C*C];
__device__ half w_kv[2*C*TD];
__device__ half w_ca[C*C];
__device__ half w_gu[(size_t)2*FF*C];
__device__ half w_d[(size_t)FF*C];
__device__ half w_ada[6*C*C];

// ---- helpers ----
__device__ __forceinline__ uint32_t smem_u32(const void* p) {
    uint32_t a;
    asm("{ .reg .u64 t; cvta.to.shared.u64 t, %1; cvt.u32.u64 %0, t; }" : "=r"(a) : "l"(p));
    return a;
}
__device__ __forceinline__ void cp16(uint32_t s, const void* g) {
    asm volatile("cp.async.cg.shared.global [%0], [%1], 16;" :: "r"(s), "l"(g));
}
__device__ __forceinline__ void ldsm4(uint32_t* r, uint32_t a) {
    asm volatile("ldmatrix.sync.aligned.m8n8.x4.shared.b16 {%0,%1,%2,%3}, [%4];"
        : "=r"(r[0]), "=r"(r[1]), "=r"(r[2]), "=r"(r[3]) : "r"(a));
}
__device__ __forceinline__ void ldsm4t(uint32_t* r, uint32_t a) {
    asm volatile("ldmatrix.sync.aligned.m8n8.x4.trans.shared.b16 {%0,%1,%2,%3}, [%4];"
        : "=r"(r[0]), "=r"(r[1]), "=r"(r[2]), "=r"(r[3]) : "r"(a));
}
__device__ __forceinline__ void mma16816(float* d, const uint32_t* a, uint32_t b0, uint32_t b1) {
    asm volatile("mma.sync.aligned.m16n8k16.row.col.f32.f16.f16.f32 "
        "{%0,%1,%2,%3}, {%4,%5,%6,%7}, {%8,%9}, {%0,%1,%2,%3};"
        : "+f"(d[0]), "+f"(d[1]), "+f"(d[2]), "+f"(d[3])
        : "r"(a[0]), "r"(a[1]), "r"(a[2]), "r"(a[3]), "r"(b0), "r"(b1));
}
__device__ __forceinline__ uint32_t ex2h2(float a, float b) {
    uint32_t h;
    asm("{ .reg .b32 t;\n\t"
        "cvt.rn.f16x2.f32 t, %2, %1;\n\t"
        "ex2.approx.f16x2 %0, t; }"
        : "=r"(h) : "f"(a), "f"(b));
    return h;
}
__device__ __forceinline__ float siluf(float v) { return v / (1.f + __expf(-v)); }

// ---- pipelined fp16 mma GEMM, K-chunk 64, 4-stage, fused epilogues ----
// EPI: 0 = float out (+ optional residual x + gate*acc)
//      2 = swiglu (interleaved gate/up) -> half [M][FF]
//      3 = SA qkv: rope q,k -> qh,kh; v row-major
//      4 = CA q   5 = CA kv
#define NSTAGE 4
#define STG 49152     // A 16K | B 32K

template<int EPI>
__global__ void __launch_bounds__(256) gmma(
    const half* __restrict__ Ax, const half* __restrict__ B0,
    void* __restrict__ Cout, int M, int N, int K,
    const float* __restrict__ resx, const float* __restrict__ mods,
    const float* __restrict__ bias, int goff,
    const float* __restrict__ fc, const float* __restrict__ fs,
    half* __restrict__ khp, half* __restrict__ vtp, int Lk)
{
    extern __shared__ char smem[];
    uint32_t sb = smem_u32(smem);
    const int tid = threadIdx.x, lane = tid & 31, wid = tid >> 5;
    const int wm = (wid & 1) << 6;
    const int wn = (wid >> 1) << 6;
    const int tM = blockIdx.y << 7, tN = blockIdx.x << 8;

    float acc[4][8][4];
#pragma unroll
    for (int f = 0; f < 4; f++)
#pragma unroll
        for (int n = 0; n < 8; n++)
#pragma unroll
            for (int v = 0; v < 4; v++) acc[f][n][v] = 0.f;

    const int kIters = K >> 6;

    auto load_stage = [&](int s, int k0) {
#pragma unroll
        for (int i = 0; i < 12; i++) {
            int id = tid + (i << 8);
            const half* g; uint32_t dst;
            if (id < 1024) {
                int row = id >> 3, c = id & 7;
                g = Ax + (size_t)(tM + row) * K + k0 + (c << 3);
                dst = sb + s * STG + row * 128 + ((c ^ (row & 7)) << 4);
            } else {
                int a = id - 1024;
                int row = a >> 3, c = a & 7;
                g = B0 + (size_t)(tN + row) * K + k0 + (c << 3);
                dst = sb + s * STG + 16384 + row * 128 + ((c ^ (row & 7)) << 4);
            }
            cp16(dst, g);
        }
    };

    for (int s = 0; s < NSTAGE - 1; s++) {
        load_stage(s, s << 6);
        asm volatile("cp.async.commit_group;");
    }

    const int lrow = lane & 15, lch = lane >> 4;

    for (int it = 0; it < kIters; it++) {
        asm volatile("cp.async.wait_group 2;");
        __syncthreads();
        if (it + NSTAGE - 1 < kIters)
            load_stage((it + NSTAGE - 1) % NSTAGE, (it + NSTAGE - 1) << 6);
        asm volatile("cp.async.commit_group;");

        uint32_t stg = sb + (uint32_t)(it % NSTAGE) * STG;
#pragma unroll
        for (int ks = 0; ks < 4; ks++) {
            int ch = (ks << 1) + lch;
            uint32_t a[4][4], b[4][4];
#pragma unroll
            for (int f = 0; f < 4; f++) {
                int row = wm + (f << 4) + lrow;
                ldsm4(a[f], stg + row * 128 + ((ch ^ (row & 7)) << 4));
            }
#pragma unroll
            for (int p = 0; p < 4; p++) {
                int row = wn + (p << 4) + lrow;
                ldsm4(b[p], stg + 16384u + row * 128 + ((ch ^ (row & 7)) << 4));
            }
#pragma unroll
            for (int f = 0; f < 4; f++)
#pragma unroll
                for (int n = 0; n < 8; n++)
                    mma16816(acc[f][n], a[f], b[n >> 1][n & 1], b[n >> 1][2 + (n & 1)]);
        }
    }

    const int bb = (EPI == 5) ? 0 : (tM >> 11);
#pragma unroll
    for (int f = 0; f < 4; f++) {
        int r0 = tM + wm + (f << 4) + (lane >> 2);
#pragma unroll
        for (int n = 0; n < 8; n++) {
            int col = tN + wn + (n << 3) + ((lane & 3) << 1);
            float v0 = acc[f][n][0], v1 = acc[f][n][1];
            float v2 = acc[f][n][2], v3 = acc[f][n][3];
            if (EPI == 0) {
                float* Cf = (float*)Cout;
                if (resx) {
                    float g0 = 1.f, g1 = 1.f;
                    if (mods) {
                        g0 = mods[(size_t)bb * 6 * C + goff + col]     + bias[goff + col];
                        g1 = mods[(size_t)bb * 6 * C + goff + col + 1] + bias[goff + col + 1];
                    }
                    v0 = resx[(size_t)r0 * N + col]         + g0 * v0;
                    v1 = resx[(size_t)r0 * N + col + 1]     + g1 * v1;
                    v2 = resx[(size_t)(r0+8) * N + col]     + g0 * v2;
                    v3 = resx[(size_t)(r0+8) * N + col + 1] + g1 * v3;
                }
                *(float2*)(Cf + (size_t)r0 * N + col)       = make_float2(v0, v1);
                *(float2*)(Cf + (size_t)(r0 + 8) * N + col) = make_float2(v2, v3);
            } else if (EPI == 2) {
                half* act = (half*)Cout;
                int oc = col >> 1;
                act[(size_t)r0 * FF + oc]       = __float2half(siluf(v0) * v1);
                act[(size_t)(r0 + 8) * FF + oc] = __float2half(siluf(v2) * v3);
            } else if (EPI == 3) {
                int l0 = r0 & 2047, l1 = (r0 + 8) & 2047;
                int sec = col >> 10, cc = col & 1023;
                int h = cc >> 6, d = cc & 63, p = d >> 1;
                int z = bb * H + h;
                if (sec < 2) {
                    float c0 = fc[l0*32+p], s0 = fs[l0*32+p];
                    float c1 = fc[l1*32+p], s1 = fs[l1*32+p];
                    float a0 = v0*c0 - v1*s0, b0 = v0*s0 + v1*c0;
                    float a1 = v2*c1 - v3*s1, b1 = v2*s1 + v3*c1;
                    half* dst;
                    if (sec == 0) { a0*=SCL; b0*=SCL; a1*=SCL; b1*=SCL; dst = (half*)Cout; }
                    else dst = khp;
                    *(half2*)(dst + ((size_t)z * L + l0) * 64 + d) = __floats2half2_rn(a0, b0);
                    *(half2*)(dst + ((size_t)z * L + l1) * 64 + d) = __floats2half2_rn(a1, b1);
                } else {
                    *(half2*)(vtp + ((size_t)z * L + l0) * 64 + d) = __floats2half2_rn(v0, v1);
                    *(half2*)(vtp + ((size_t)z * L + l1) * 64 + d) = __floats2half2_rn(v2, v3);
                }
            } else if (EPI == 4) {
                int l0 = r0 & 2047, l1 = (r0 + 8) & 2047;
                int h = col >> 6, d = col & 63;
                int z = bb * H + h;
                half* qh = (half*)Cout;
                *(half2*)(qh + ((size_t)z * L + l0) * 64 + d) = __floats2half2_rn(v0*SCL, v1*SCL);
                *(half2*)(qh + ((size_t)z * L + l1) * 64 + d) = __floats2half2_rn(v2*SCL, v3*SCL);
            } else if (EPI == 5) {
                int b2 = r0 >> 9;
                int k0 = r0 & 511, k1 = (r0 + 8) & 511;
                int sec = col >> 10, cc = col & 1023;
                int h = cc >> 6, d = cc & 63;
                int z = b2 * H + h;
                half* dst = (sec == 0) ? (half*)Cout : vtp;
                *(half2*)(dst + ((size_t)z * L2 + k0) * 64 + d) = __floats2half2_rn(v0, v1);
                *(half2*)(dst + ((size_t)z * L2 + k1) * 64 + d) = __floats2half2_rn(v2, v3);
            }
        }
    }
}

#define GSM (NSTAGE * STG)
template<int EPI>
static inline void launch_gmma(const half* A, const half* Bw, void* Co, int M, int N, int K,
                               const float* resx, const float* mods, const float* bias, int goff,
                               const float* fc, const float* fs, half* kh, half* vt, int Lk) {
    cudaFuncSetAttribute(gmma<EPI>, cudaFuncAttributeMaxDynamicSharedMemorySize, GSM);
    gmma<EPI><<<dim3(N/256, M/128), 256, GSM>>>(A, Bw, Co, M, N, K,
                                                resx, mods, bias, goff, fc, fs, kh, vt, Lk);
}

// ---- fused flash attention: 4 KV buffers, wait_group 2, one sync/chunk ----
#define FA_SMEM (16384 + 4 * 16384)   // Q 16K | 4 x KV 16K = 80K

__global__ void __launch_bounds__(256) fattn_kernel(
    const half* __restrict__ Qg, const half* __restrict__ Kg, const half* __restrict__ Vg,
    half* __restrict__ act, int Lk)
{
    extern __shared__ char smem[];
    uint32_t sb = smem_u32(smem);
    const uint32_t sQ = sb, sKV = sb + 16384;
    const int tid = threadIdx.x, lane = tid & 31, wid = tid >> 5;
    const int lrow = lane & 15, lch = lane >> 4;
    const int z = blockIdx.y;
    const int q0 = blockIdx.x << 7;
    const half* Qz = Qg + ((size_t)z * L + q0) * D;
    const half* Kz = Kg + (size_t)z * Lk * D;
    const half* Vz = Vg + (size_t)z * Lk * D;
    const uint32_t ONE2 = 0x3C003C00u;

    for (int id = tid; id < 1024; id += 256) {
        int row = id >> 3, c = id & 7;
        cp16(sQ + row * 128 + ((c ^ (row & 7)) << 4), Qz + row * D + c * 8);
    }
    auto load_kv = [&](int j) {
        uint32_t base = sKV + (uint32_t)(j & 3) * 16384;
        for (int id = tid; id < 1024; id += 256) {
            int row = (id >> 3) & 63, c = id & 7;
            const half* src = (id < 512) ? Kz : Vz;
            uint32_t off = (id < 512) ? 0u : 8192u;
            cp16(base + off + row * 128 + ((c ^ (row & 7)) << 4),
                 src + (size_t)(j * 64 + row) * D + c * 8);
        }
    };
    const int nch = Lk >> 6;    // >= 8 always
    load_kv(0);
    asm volatile("cp.async.commit_group;");
    load_kv(1);
    asm volatile("cp.async.commit_group;");
    load_kv(2);
    asm volatile("cp.async.commit_group;");

    float accO[8][4], accL[4];
#pragma unroll
    for (int n = 0; n < 8; n++)
#pragma unroll
        for (int v = 0; v < 4; v++) accO[n][v] = 0.f;
#pragma unroll
    for (int v = 0; v < 4; v++) accL[v] = 0.f;
    float m0 = -1e30f, m1 = -1e30f;
    uint32_t aq[4][4];

    for (int j = 0; j < nch; j++) {
        asm volatile("cp.async.wait_group 2;");
        __syncthreads();
        // prefetch j+3 into the slot freed at iteration j-1 (all readers passed the barrier above)
        if (j + 3 < nch) load_kv(j + 3);
        asm volatile("cp.async.commit_group;");

        if (j == 0) {
#pragma unroll
            for (int ks = 0; ks < 4; ks++) {
                int row = (wid << 4) + lrow;
                int ch = (ks << 1) + lch;
                ldsm4(aq[ks], sQ + row * 128 + ((ch ^ (row & 7)) << 4));
            }
        }
        uint32_t bK = sKV + (uint32_t)(j & 3) * 16384;
        uint32_t bV = bK + 8192;

        float s[8][4];
#pragma unroll
        for (int n = 0; n < 8; n++)
#pragma unroll
            for (int v = 0; v < 4; v++) s[n][v] = 0.f;
#pragma unroll
        for (int ks = 0; ks < 4; ks++) {
            uint32_t b[4][4];
            int ch = (ks << 1) + lch;
#pragma unroll
            for (int p = 0; p < 4; p++) {
                int row = (p << 4) + lrow;
                ldsm4(b[p], bK + row * 128 + ((ch ^ (row & 7)) << 4));
            }
#pragma unroll
            for (int n = 0; n < 8; n++)
                mma16816(s[n], aq[ks], b[n >> 1][n & 1], b[n >> 1][2 + (n & 1)]);
        }

        float mt0 = -1e30f, mt1 = -1e30f;
#pragma unroll
        for (int n = 0; n < 8; n++) {
            mt0 = fmaxf(mt0, fmaxf(s[n][0], s[n][1]));
            mt1 = fmaxf(mt1, fmaxf(s[n][2], s[n][3]));
        }
        mt0 = fmaxf(mt0, __shfl_xor_sync(0xffffffff, mt0, 1));
        mt0 = fmaxf(mt0, __shfl_xor_sync(0xffffffff, mt0, 2));
        mt1 = fmaxf(mt1, __shfl_xor_sync(0xffffffff, mt1, 1));
        mt1 = fmaxf(mt1, __shfl_xor_sync(0xffffffff, mt1, 2));
        float M0 = fmaxf(m0, mt0), M1 = fmaxf(m1, mt1);
        float c0 = exp2f(m0 - M0), c1 = exp2f(m1 - M1);
        m0 = M0; m1 = M1;

        uint32_t pa[4][4];
#pragma unroll
        for (int t = 0; t < 4; t++) {
            pa[t][0] = ex2h2(s[2*t][0]   - M0, s[2*t][1]   - M0);
            pa[t][1] = ex2h2(s[2*t][2]   - M1, s[2*t][3]   - M1);
            pa[t][2] = ex2h2(s[2*t+1][0] - M0, s[2*t+1][1] - M0);
            pa[t][3] = ex2h2(s[2*t+1][2] - M1, s[2*t+1][3] - M1);
        }

#pragma unroll
        for (int n = 0; n < 8; n++) {
            accO[n][0] *= c0; accO[n][1] *= c0;
            accO[n][2] *= c1; accO[n][3] *= c1;
        }
        accL[0] *= c0; accL[2] *= c1;
#pragma unroll
        for (int kt = 0; kt < 4; kt++)
            mma16816(accL, pa[kt], ONE2, ONE2);

#pragma unroll
        for (int kt = 0; kt < 4; kt++) {
            uint32_t bt[4][4];
#pragma unroll
            for (int p = 0; p < 4; p++) {
                int row = (kt << 4) + lrow;
                int ch = (p << 1) + lch;
                ldsm4t(bt[p], bV + row * 128 + ((ch ^ (row & 7)) << 4));
            }
#pragma unroll
            for (int n = 0; n < 8; n++)
                mma16816(accO[n], pa[kt], bt[n >> 1][(n & 1) << 1], bt[n >> 1][((n & 1) << 1) + 1]);
        }
    }

    float inv0 = 1.f / accL[0], inv1 = 1.f / accL[2];
    int b = z >> 4, h = z & 15;
    int row0 = q0 + (wid << 4) + (lane >> 2);
    half* a0 = act + ((size_t)(b * L + row0) * C) + h * 64;
    half* a1 = a0 + (size_t)8 * C;
#pragma unroll
    for (int n = 0; n < 8; n++) {
        int col = (n << 3) + ((lane & 3) << 1);
        *(half2*)(a0 + col) = __floats2half2_rn(accO[n][0] * inv0, accO[n][1] * inv0);
        *(half2*)(a1 + col) = __floats2half2_rn(accO[n][2] * inv1, accO[n][3] * inv1);
    }
}

static inline void fattn(const half* Q, const half* K, const half* V, half* act, int Lk) {
    cudaFuncSetAttribute(fattn_kernel, cudaFuncAttributeMaxDynamicSharedMemorySize, FA_SMEM);
    fattn_kernel<<<dim3(L/128, ZB), 256, FA_SMEM>>>(Q, K, V, act, Lk);
}

// ---- merged weight convert ----
struct WJob { const float* W; half* T; int K, N, rs, ro, tile0; };
struct WAll { WJob j[9]; int ntiles; };

__global__ void wconvert_all_kernel(WAll wa) {
    __shared__ float t[32][33];
    int g = blockIdx.x;
    int ji = 0;
#pragma unroll
    for (int k = 1; k < 9; k++) if (g >= wa.j[k].tile0) ji = k;
    WJob w = wa.j[ji];
    int lt = g - w.tile0;
    int nx = w.N >> 5;
    int n0 = (lt % nx) << 5, k0 = (lt / nx) << 5;
    int tx = threadIdx.x, ty = threadIdx.y;
#pragma unroll
    for (int i = 0; i < 32; i += 8) t[ty + i][tx] = w.W[(size_t)(k0 + ty + i) * w.N + n0 + tx];
    __syncthreads();
#pragma unroll
    for (int i = 0; i < 32; i += 8)
        w.T[(size_t)((n0 + ty + i) * w.rs + w.ro) * w.K + k0 + tx] = __float2half(t[tx][ty + i]);
}

__global__ void silu2h_kernel(const float* __restrict__ in, half* __restrict__ o) {
    int i = blockIdx.x * blockDim.x + threadIdx.x;
    if (i >= 128 * C) return;
    o[i] = (i < B * C) ? __float2half(siluf(in[i])) : __float2half(0.f);
}
__global__ void aconvert_kernel(const float* __restrict__ a, half* __restrict__ o, size_t n) {
    size_t i = (size_t)blockIdx.x * blockDim.x + threadIdx.x;
    if (i >= n) return;
    o[i] = __float2half(a[i]);
}

__global__ void rmsnorm_kernel(const float* __restrict__ x, const float* __restrict__ w,
                               const float* __restrict__ mods, const float* __restrict__ bias,
                               int sh_off, int sc_off, half* __restrict__ o) {
    int row = blockIdx.x, b = row / L;
    const float4* xr = (const float4*)(x + (size_t)row * C);
    float4 v = xr[threadIdx.x];
    float s = v.x*v.x + v.y*v.y + v.z*v.z + v.w*v.w;
    __shared__ float red[8];
#pragma unroll
    for (int o2 = 16; o2 > 0; o2 >>= 1) s += __shfl_xor_sync(0xffffffff, s, o2);
    if ((threadIdx.x & 31) == 0) red[threadIdx.x >> 5] = s;
    __syncthreads();
    s = red[threadIdx.x & 7];
#pragma unroll
    for (int o2 = 4; o2 > 0; o2 >>= 1) s += __shfl_xor_sync(0xffffffff, s, o2);
    float inv = rsqrtf(s / (float)C + EPS);
    int c = threadIdx.x << 2;
    float4 wv = *(const float4*)(w + c);
    float r[4] = {v.x * inv * wv.x, v.y * inv * wv.y, v.z * inv * wv.z, v.w * inv * wv.w};
    if (mods) {
        float4 sc = *(const float4*)(mods + (size_t)b * 6 * C + sc_off + c);
        float4 scb = *(const float4*)(bias + sc_off + c);
        float4 sh = *(const float4*)(mods + (size_t)b * 6 * C + sh_off + c);
        float4 shb = *(const float4*)(bias + sh_off + c);
        r[0] = r[0] * (1.f + sc.x + scb.x) + sh.x + shb.x;
        r[1] = r[1] * (1.f + sc.y + scb.y) + sh.y + shb.y;
        r[2] = r[2] * (1.f + sc.z + scb.z) + sh.z + shb.z;
        r[3] = r[3] * (1.f + sc.w + scb.w) + sh.w + shb.w;
    }
    half2 h0 = __floats2half2_rn(r[0], r[1]);
    half2 h1 = __floats2half2_rn(r[2], r[3]);
    uint2 pk = { *(uint32_t*)&h0, *(uint32_t*)&h1 };
    *(uint2*)(o + (size_t)row * C + c) = pk;
}

// ---- launch ----
#define GSYM(p, s) cudaGetSymbolAddress((void**)&p, s)
extern "C" void kernel_launch(void* const* d_in, const int* in_sizes, int n_in,
                              void* d_out, int out_size) {
    const float* x     = (const float*)d_in[0];
    const float* t_mod = (const float*)d_in[1];
    const float* audio = (const float*)d_in[2];
    const float* fcos  = (const float*)d_in[3];
    const float* fsin  = (const float*)d_in[4];
    const float* n1w   = (const float*)d_in[5];
    const float* n2w   = (const float*)d_in[6];
    const float* n3w   = (const float*)d_in[7];
    const float* Wqkv  = (const float*)d_in[8];
    const float* Wsa   = (const float*)d_in[9];
    const float* Wq    = (const float*)d_in[10];
    const float* Wkv   = (const float*)d_in[11];
    const float* Wca   = (const float*)d_in[12];
    const float* Wg    = (const float*)d_in[13];
    const float* Wu    = (const float*)d_in[14];
    const float* Wd    = (const float*)d_in[15];
    const float* adaW  = (const float*)d_in[16];
    const float* adaB  = (const float*)d_in[17];
    float* out = (float*)d_out;

    float *mods_p, *x_p;
    half *hid, *act, *ctx, *sm, *qh_p, *kh_p, *v_p;
    half *qkvw, *saw, *qw, *kvw, *caw, *guw, *dw, *adw;
    GSYM(mods_p, g_mods); GSYM(x_p, g_x);
    GSYM(hid, g_h); GSYM(act, g_act); GSYM(ctx, g_ctx); GSYM(sm, g_sm);
    GSYM(qh_p, g_qh); GSYM(kh_p, g_kh); GSYM(v_p, g_v);
    GSYM(qkvw, w_qkv); GSYM(saw, w_sa); GSYM(qw, w_q); GSYM(kvw, w_kv);
    GSYM(caw, w_ca); GSYM(guw, w_gu); GSYM(dw, w_d); GSYM(adw, w_ada);

    WAll wa;
    const float* Ws[9] = {Wqkv, Wsa, Wq, Wkv, Wca, Wg, Wu, Wd, adaW};
    half* Ts[9] = {qkvw, saw, qw, kvw, caw, guw, guw, dw, adw};
    int Ks[9] = {C, C, C, TD, C, C, C, FF, C};
    int Ns[9] = {3*C, C, C, 2*C, C, FF, FF, C, 6*C};
    int Rs[9] = {1, 1, 1, 1, 1, 2, 2, 1, 1};
    int Ro[9] = {0, 0, 0, 0, 0, 0, 1, 0, 0};
    int tile = 0;
    for (int i = 0; i < 9; i++) {
        wa.j[i] = {Ws[i], Ts[i], Ks[i], Ns[i], Rs[i], Ro[i], tile};
        tile += (Ks[i] >> 5) * (Ns[i] >> 5);
    }
    wa.ntiles = tile;
    wconvert_all_kernel<<<tile, dim3(32, 8)>>>(wa);

    // adaLN (M padded to 128; bias folded at consumers)
    silu2h_kernel<<<(128*C + 255)/256, 256>>>(t_mod, sm);
    launch_gmma<0>(sm, adw, mods_p, 128, 6*C, C,
                   nullptr, nullptr, nullptr, 0, nullptr, nullptr, nullptr, nullptr, 0);

    // ---- self-attention ----
    rmsnorm_kernel<<<BL, 256>>>(x, n1w, mods_p, adaB, 0, C, act);
    launch_gmma<3>(act, qkvw, qh_p, BL, 3*C, C,
                   nullptr, nullptr, nullptr, 0, fcos, fsin, kh_p, v_p, L);
    fattn(qh_p, kh_p, v_p, act, L);
    launch_gmma<0>(act, saw, x_p, BL, C, C,
                   x, mods_p, adaB, 2*C, nullptr, nullptr, nullptr, nullptr, 0);

    // ---- cross-attention ----
    rmsnorm_kernel<<<BL, 256>>>(x_p, n2w, nullptr, nullptr, 0, 0, act);
    launch_gmma<4>(act, qw, qh_p, BL, C, C,
                   nullptr, nullptr, nullptr, 0, nullptr, nullptr, nullptr, nullptr, L);
    aconvert_kernel<<<(BL2*TD + 255)/256, 256>>>(audio, ctx, (size_t)BL2*TD);
    launch_gmma<5>(ctx, kvw, kh_p, BL2, 2*C, TD,
                   nullptr, nullptr, nullptr, 0, nullptr, nullptr, nullptr, v_p, L2);
    fattn(qh_p, kh_p, v_p, act, L2);
    launch_gmma<0>(act, caw, x_p, BL, C, C,
                   x_p, nullptr, nullptr, 0, nullptr, nullptr, nullptr, nullptr, 0);

    // ---- MLP ----
    rmsnorm_kernel<<<BL, 256>>>(x_p, n3w, mods_p, adaB, 3*C, 4*C, act);
    launch_gmma<2>(act, guw, hid, BL, 2*FF, C,
                   nullptr, nullptr, nullptr, 0, nullptr, nullptr, nullptr, nullptr, 0);
    launch_gmma<0>(hid, dw, out, BL, C, FF,
                   x_p, mods_p, adaB, 5*C, nullptr, nullptr, nullptr, nullptr, 0);
}